// round 4
// baseline (speedup 1.0000x reference)
#include <cuda_runtime.h>
#include <math.h>

#define NT 256
typedef unsigned long long u64;

// f32x2 packed math (Blackwell): two fp32 FMAs per instruction
#define FMA2(d,a,b)  asm("fma.rn.f32x2 %0, %1, %2, %0;" : "+l"(d) : "l"(a), "l"(b))
#define UNPK(lo,hi,p) asm("mov.b64 {%0,%1}, %2;" : "=f"(lo), "=f"(hi) : "l"(p))
#define PK(p,lo,hi)   asm("mov.b64 %0, {%1,%2};" : "=l"(p) : "f"(lo), "f"(hi))

// ---------------- device scratch ----------------
__device__ __align__(16) float g_geo[4096];
__device__ __align__(16) float g_p16[4096];   // pattern part of pm1 + pm1_b, per (n,j)
__device__ __align__(16) float g_wq[4096];
__device__ __align__(16) float g_wk[4096];
__device__ __align__(16) float g_wv[4096];
__device__ __align__(16) float g_bq[64];
__device__ __align__(16) float g_bk[64];
__device__ __align__(16) float g_bv[64];

// ---------------- prep: geo, P16, fused QKV weights ----------------
__global__ void esa_prep_kernel(const float* __restrict__ points,
                                const int*   __restrict__ adjacency,
                                const float* __restrict__ in_w,
                                const float* __restrict__ in_b,
                                const float* __restrict__ pattern,
                                const float* __restrict__ pm1_w,
                                const float* __restrict__ pm1_b,
                                const float* __restrict__ q_w, const float* __restrict__ q_b,
                                const float* __restrict__ k_w, const float* __restrict__ k_b,
                                const float* __restrict__ v_w, const float* __restrict__ v_b)
{
    const int gtid = blockIdx.x * blockDim.x + threadIdx.x;
    const int gstride = gridDim.x * blockDim.x;
    const float scale = 0.3535533905932738f; // 1/sqrt(8)

    for (int idx = gtid; idx < 4096; idx += gstride) {
        int n = idx >> 6, m = idx & 63;
        float dx = points[n*3+0] - points[m*3+0];
        float dy = points[n*3+1] - points[m*3+1];
        float dz = points[n*3+2] - points[m*3+2];
        float dist = sqrtf(dx*dx + dy*dy + dz*dz + 1e-12f);
        g_geo[idx] = (adjacency[idx] > 0) ? 0.5f : (-0.1f / (1.0f + dist));
    }
    // P16[n][j] = pm1_b[j] + sum_p pattern[n][p] * pm1_w[j][64+p]
    for (int idx = gtid; idx < 4096; idx += gstride) {
        int n = idx >> 6, j = idx & 63;
        float s = pm1_b[j];
        const float* wr = pm1_w + j*80 + 64;
        const float* pr = pattern + n*16;
        #pragma unroll
        for (int p = 0; p < 16; p++) s += pr[p] * wr[p];
        g_p16[idx] = s;
    }
    // W_eff[o][u] = sum_t in_w[o][t] * x_w[t][u]   (q scaled by 1/sqrt(D))
    for (int idx = gtid; idx < 3*4096; idx += gstride) {
        int which = idx >> 12;
        int o = (idx >> 6) & 63;
        int u = idx & 63;
        const float* wi = in_w + which*4096 + o*64;
        const float* wx = (which==0) ? q_w : (which==1) ? k_w : v_w;
        float s = 0.f;
        #pragma unroll 4
        for (int t = 0; t < 64; t++) s += wi[t] * wx[t*64 + u];
        if (which == 0) s *= scale;
        float* dst = (which==0) ? g_wq : (which==1) ? g_wk : g_wv;
        dst[o*64 + u] = s;
    }
    for (int idx = gtid; idx < 192; idx += gstride) {
        int which = idx >> 6, o = idx & 63;
        const float* wi = in_w + which*4096 + o*64;
        const float* bx = (which==0) ? q_b : (which==1) ? k_b : v_b;
        float s = in_b[which*64 + o];
        for (int t = 0; t < 64; t++) s += wi[t] * bx[t];
        if (which == 0) s *= scale;
        float* dst = (which==0) ? g_bq : (which==1) ? g_bk : g_bv;
        dst[o] = s;
    }
}

// ---------------- f32x2 GEMM: out[n][j] = act(bias + in[n][:]·W[j][:]) ----------------
// in: smem, stride sin. W: GLOBAL (L1/L2-cached), row stride swg, K=64.
// BIASMAT: bias is a 64x64 matrix (g_p16) instead of a vector.
template<bool RELU, bool BIASMAT>
__device__ __forceinline__ void gemm64x2(const float* __restrict__ in, int sin,
                                         const float* __restrict__ wg, int swg,
                                         const float* __restrict__ bias,
                                         float* __restrict__ outp, int so, int tid)
{
    const int n0 = (tid >> 4) << 2;
    const int j0 = tid & 15;
    u64 acc[4][4];
    #pragma unroll
    for (int i = 0; i < 4; i++)
        #pragma unroll
        for (int j = 0; j < 4; j++) acc[i][j] = 0ull;

    const float* ap = in + n0*sin;
    const float* wp0 = wg + j0*swg;
    const float* wp1 = wp0 + 16*swg;
    const float* wp2 = wp1 + 16*swg;
    const float* wp3 = wp2 + 16*swg;

    #pragma unroll 4
    for (int k = 0; k < 64; k += 4) {
        ulonglong2 a[4], b[4];
        a[0] = *(const ulonglong2*)(ap + k);
        a[1] = *(const ulonglong2*)(ap + sin + k);
        a[2] = *(const ulonglong2*)(ap + 2*sin + k);
        a[3] = *(const ulonglong2*)(ap + 3*sin + k);
        b[0] = __ldg((const ulonglong2*)(wp0 + k));
        b[1] = __ldg((const ulonglong2*)(wp1 + k));
        b[2] = __ldg((const ulonglong2*)(wp2 + k));
        b[3] = __ldg((const ulonglong2*)(wp3 + k));
        #pragma unroll
        for (int i = 0; i < 4; i++)
            #pragma unroll
            for (int j = 0; j < 4; j++) {
                FMA2(acc[i][j], a[i].x, b[j].x);
                FMA2(acc[i][j], a[i].y, b[j].y);
            }
    }
    #pragma unroll
    for (int j = 0; j < 4; j++) {
        int jj = j0 + 16*j;
        float bj = BIASMAT ? 0.f : __ldg(bias + jj);
        #pragma unroll
        for (int i = 0; i < 4; i++) {
            float lo, hi; UNPK(lo, hi, acc[i][j]);
            float v = lo + hi + bj;
            if (BIASMAT) v += __ldg(bias + (n0+i)*64 + jj);
            if (RELU) v = fmaxf(v, 0.f);
            outp[(n0+i)*so + jj] = v;
        }
    }
}

// mo projection with fused +geo +residual epilogue
__device__ __forceinline__ void gemm_mo_x2(const float* __restrict__ in,
                                           const float* __restrict__ wg,
                                           const float* __restrict__ mo_b,
                                           const float* __restrict__ pf,
                                           float* __restrict__ outp, int tid)
{
    const int n0 = (tid >> 4) << 2;
    const int j0 = tid & 15;
    u64 acc[4][4];
    #pragma unroll
    for (int i = 0; i < 4; i++)
        #pragma unroll
        for (int j = 0; j < 4; j++) acc[i][j] = 0ull;

    const float* ap = in + n0*68;
    const float* wp0 = wg + j0*64;
    const float* wp1 = wp0 + 1024;
    const float* wp2 = wp1 + 1024;
    const float* wp3 = wp2 + 1024;

    #pragma unroll 4
    for (int k = 0; k < 64; k += 4) {
        ulonglong2 a[4], b[4];
        a[0] = *(const ulonglong2*)(ap + k);
        a[1] = *(const ulonglong2*)(ap + 68 + k);
        a[2] = *(const ulonglong2*)(ap + 136 + k);
        a[3] = *(const ulonglong2*)(ap + 204 + k);
        b[0] = __ldg((const ulonglong2*)(wp0 + k));
        b[1] = __ldg((const ulonglong2*)(wp1 + k));
        b[2] = __ldg((const ulonglong2*)(wp2 + k));
        b[3] = __ldg((const ulonglong2*)(wp3 + k));
        #pragma unroll
        for (int i = 0; i < 4; i++)
            #pragma unroll
            for (int j = 0; j < 4; j++) {
                FMA2(acc[i][j], a[i].x, b[j].x);
                FMA2(acc[i][j], a[i].y, b[j].y);
            }
    }
    #pragma unroll
    for (int j = 0; j < 4; j++) {
        int jj = j0 + 16*j;
        float bj = __ldg(mo_b + jj);
        #pragma unroll
        for (int i = 0; i < 4; i++) {
            int nn = n0 + i;
            float lo, hi; UNPK(lo, hi, acc[i][j]);
            outp[nn*68 + jj] = lo + hi + bj + __ldg(g_geo + nn*64 + jj) + pf[nn*68 + jj];
        }
    }
}

// conv tap macro: 4 outputs per thread with shifted 3-tap window
#define CONVTAP(XP, CC, W0, W1, W2) { \
    const float* xr = (XP) + (CC)*68 + base; \
    float4 xv = *(const float4*)xr; float2 xt = *(const float2*)(xr+4); \
    a0 += (W0)*xv.x + (W1)*xv.y + (W2)*xv.z; \
    a1 += (W0)*xv.y + (W1)*xv.z + (W2)*xv.w; \
    a2 += (W0)*xv.z + (W1)*xv.w + (W2)*xt.x; \
    a3 += (W0)*xv.w + (W1)*xt.x + (W2)*xt.y; }

// ---------------- main fused kernel: one CTA per batch element ----------------
// smem (floats, stride 68 rows):
//   X  0      (4352) : x -> V
//   Y1 4352   (4352) : conv mid (16x68) -> final out (64x65)
//   CB 8704   (4352) : combined -> Q -> CTX
//   T  13056  (4352) : pm1 tmp -> K -> h
//   PF 17408  (4352) : residual
#define SMEM_FLOATS 21760

__global__ void __launch_bounds__(NT, 2)
esa_main_kernel(const float* __restrict__ x,
                const float* __restrict__ conv1_w, const float* __restrict__ conv1_b,
                const float* __restrict__ conv2_w, const float* __restrict__ conv2_b,
                const float* __restrict__ pm1_w,
                const float* __restrict__ pm2_w, const float* __restrict__ pm2_b,
                const float* __restrict__ mo_w,  const float* __restrict__ mo_b,
                const float* __restrict__ out_w, const float* __restrict__ out_b,
                const float* __restrict__ ln_g,  const float* __restrict__ ln_b,
                float* __restrict__ out)
{
    extern __shared__ float sm[];
    const int tid = threadIdx.x;
    const int b = blockIdx.x;
    float* X  = sm;
    float* Y1 = sm + 4352;
    float* CB = sm + 8704;
    float* T  = sm + 13056;
    float* PF = sm + 17408;

    // ---- load x (vectorized) + pads ----
    const float* xg = x + (size_t)b * 4096;
    for (int idx4 = tid; idx4 < 1024; idx4 += NT) {
        float4 v = __ldg((const float4*)xg + idx4);
        int c = idx4 >> 4, n = (idx4 & 15) << 2;
        float* r = X + c*68 + 1 + n;
        r[0] = v.x; r[1] = v.y; r[2] = v.z; r[3] = v.w;
    }
    if (tid < 64) { X[tid*68] = 0.f; X[tid*68 + 65] = 0.f; }
    if (tid < 16) { Y1[tid*68] = 0.f; Y1[tid*68 + 65] = 0.f; }
    __syncthreads();

    // ---- 4-scale conv stack, weights straight from global (L1-cached) ----
    for (int s = 0; s < 4; s++) {
        {
            int o = tid >> 4, nq = tid & 15, base = nq*4;
            const float* wr = conv1_w + s*3072 + o*192;
            float a0=0.f, a1=0.f, a2=0.f, a3=0.f;
            #pragma unroll 4
            for (int c = 0; c < 64; c += 4) {
                float4 wA = __ldg((const float4*)(wr + c*3));
                float4 wB = __ldg((const float4*)(wr + c*3 + 4));
                float4 wC = __ldg((const float4*)(wr + c*3 + 8));
                CONVTAP(X, c+0, wA.x, wA.y, wA.z);
                CONVTAP(X, c+1, wA.w, wB.x, wB.y);
                CONVTAP(X, c+2, wB.z, wB.w, wC.x);
                CONVTAP(X, c+3, wC.y, wC.z, wC.w);
            }
            float bb = __ldg(conv1_b + s*16 + o);
            float* yr = Y1 + o*68 + 1 + base;
            yr[0] = fmaxf(a0+bb, 0.f); yr[1] = fmaxf(a1+bb, 0.f);
            yr[2] = fmaxf(a2+bb, 0.f); yr[3] = fmaxf(a3+bb, 0.f);
        }
        __syncthreads();
        {
            int o = tid >> 4, nq = tid & 15, base = nq*4;
            const float* wr = conv2_w + s*768 + o*48;
            float a0=0.f, a1=0.f, a2=0.f, a3=0.f;
            #pragma unroll
            for (int c = 0; c < 16; c += 4) {
                float4 wA = __ldg((const float4*)(wr + c*3));
                float4 wB = __ldg((const float4*)(wr + c*3 + 4));
                float4 wC = __ldg((const float4*)(wr + c*3 + 8));
                CONVTAP(Y1, c+0, wA.x, wA.y, wA.z);
                CONVTAP(Y1, c+1, wA.w, wB.x, wB.y);
                CONVTAP(Y1, c+2, wB.z, wB.w, wC.x);
                CONVTAP(Y1, c+3, wC.y, wC.z, wC.w);
            }
            float bb = __ldg(conv2_b + s*16 + o);
            int ch = s*16 + o;
            CB[(base+0)*68 + ch] = fmaxf(a0+bb, 0.f);
            CB[(base+1)*68 + ch] = fmaxf(a1+bb, 0.f);
            CB[(base+2)*68 + ch] = fmaxf(a2+bb, 0.f);
            CB[(base+3)*68 + ch] = fmaxf(a3+bb, 0.f);
        }
        __syncthreads();
    }

    // ---- pattern MLP (pattern part folded into P16 bias matrix) ----
    gemm64x2<true,  true >(CB, 68, pm1_w, 80, g_p16, T, 68, tid);
    __syncthreads();
    gemm64x2<false, false>(T, 68, pm2_w, 64, pm2_b, PF, 68, tid);
    __syncthreads();

    // ---- fused Q/K/V (qkv + in_w collapsed, 1/sqrt(D) folded into Q) ----
    gemm64x2<false, false>(PF, 68, g_wq, 64, g_bq, CB, 68, tid);  // Q -> CB
    gemm64x2<false, false>(PF, 68, g_wk, 64, g_bk, T,  68, tid);  // K -> T
    gemm64x2<false, false>(PF, 68, g_wv, 64, g_bv, X,  68, tid);  // V -> X
    __syncthreads();

    // ---- attention: thread = (n, head); warp shares head -> broadcast K/V ----
    // CTX overwrites Q in place: each (row, head-block) cell owned by one thread.
    {
        const int n  = tid & 63;
        const int hb = tid >> 6;       // 0..3
        #pragma unroll
        for (int it = 0; it < 2; it++) {
            const int h8 = (hb + 4*it) * 8;
            float* qr = CB + n*68 + h8;
            ulonglong2 qa = *(const ulonglong2*)qr;        // q0..q3
            ulonglong2 qb = *(const ulonglong2*)(qr + 4);  // q4..q7
            float sc[64];
            float mx = -3.0e38f;
            #pragma unroll
            for (int m = 0; m < 64; m++) {
                const float* kr = T + m*68 + h8;
                ulonglong2 ka = *(const ulonglong2*)kr;
                ulonglong2 kb = *(const ulonglong2*)(kr + 4);
                u64 d = 0ull;
                FMA2(d, qa.x, ka.x); FMA2(d, qa.y, ka.y);
                FMA2(d, qb.x, kb.x); FMA2(d, qb.y, kb.y);
                float lo, hi; UNPK(lo, hi, d);
                float sv = lo + hi;
                sc[m] = sv; mx = fmaxf(mx, sv);
            }
            u64 c01 = 0ull, c23 = 0ull, c45 = 0ull, c67 = 0ull;
            float sum = 0.f;
            #pragma unroll
            for (int m = 0; m < 64; m++) {
                float e = __expf(sc[m] - mx);
                sum += e;
                u64 ee; PK(ee, e, e);
                const float* vr = X + m*68 + h8;
                ulonglong2 va = *(const ulonglong2*)vr;
                ulonglong2 vb = *(const ulonglong2*)(vr + 4);
                FMA2(c01, ee, va.x); FMA2(c23, ee, va.y);
                FMA2(c45, ee, vb.x); FMA2(c67, ee, vb.y);
            }
            float inv = 1.f / sum;
            float c0,c1,c2,c3,c4,c5,c6,c7;
            UNPK(c0,c1,c01); UNPK(c2,c3,c23); UNPK(c4,c5,c45); UNPK(c6,c7,c67);
            float4 o1 = make_float4(c0*inv, c1*inv, c2*inv, c3*inv);
            float4 o2 = make_float4(c4*inv, c5*inv, c6*inv, c7*inv);
            *(float4*)qr       = o1;   // CTX into Q slot (race-free)
            *(float4*)(qr + 4) = o2;
        }
    }
    __syncthreads();

    // ---- mo + geo + residual -> h (T) ----
    gemm_mo_x2(CB, mo_w, mo_b, PF, T, tid);
    __syncthreads();

    // ---- LayerNorm over C (in place in T) ----
    {
        int n = tid >> 2, g = tid & 3;
        float* hr = T + n*68 + g*16;
        float4 v0 = *(const float4*)(hr);
        float4 v1 = *(const float4*)(hr + 4);
        float4 v2 = *(const float4*)(hr + 8);
        float4 v3 = *(const float4*)(hr + 12);
        float s  = v0.x+v0.y+v0.z+v0.w + v1.x+v1.y+v1.z+v1.w
                 + v2.x+v2.y+v2.z+v2.w + v3.x+v3.y+v3.z+v3.w;
        float s2 = v0.x*v0.x+v0.y*v0.y+v0.z*v0.z+v0.w*v0.w
                 + v1.x*v1.x+v1.y*v1.y+v1.z*v1.z+v1.w*v1.w
                 + v2.x*v2.x+v2.y*v2.y+v2.z*v2.z+v2.w*v2.w
                 + v3.x*v3.x+v3.y*v3.y+v3.z*v3.z+v3.w*v3.w;
        s  += __shfl_xor_sync(0xffffffffu, s, 1);
        s  += __shfl_xor_sync(0xffffffffu, s, 2);
        s2 += __shfl_xor_sync(0xffffffffu, s2, 1);
        s2 += __shfl_xor_sync(0xffffffffu, s2, 2);
        float mu  = s * 0.015625f;
        float var = s2 * 0.015625f - mu*mu;
        float r = rsqrtf(var + 1e-5f);
        int cb = g*16;
        float4 g0 = __ldg((const float4*)(ln_g + cb));
        float4 g1 = __ldg((const float4*)(ln_g + cb + 4));
        float4 g2 = __ldg((const float4*)(ln_g + cb + 8));
        float4 g3 = __ldg((const float4*)(ln_g + cb + 12));
        float4 b0 = __ldg((const float4*)(ln_b + cb));
        float4 b1 = __ldg((const float4*)(ln_b + cb + 4));
        float4 b2 = __ldg((const float4*)(ln_b + cb + 8));
        float4 b3 = __ldg((const float4*)(ln_b + cb + 12));
        hr[0]  = (v0.x-mu)*r*g0.x + b0.x;  hr[1]  = (v0.y-mu)*r*g0.y + b0.y;
        hr[2]  = (v0.z-mu)*r*g0.z + b0.z;  hr[3]  = (v0.w-mu)*r*g0.w + b0.w;
        hr[4]  = (v1.x-mu)*r*g1.x + b1.x;  hr[5]  = (v1.y-mu)*r*g1.y + b1.y;
        hr[6]  = (v1.z-mu)*r*g1.z + b1.z;  hr[7]  = (v1.w-mu)*r*g1.w + b1.w;
        hr[8]  = (v2.x-mu)*r*g2.x + b2.x;  hr[9]  = (v2.y-mu)*r*g2.y + b2.y;
        hr[10] = (v2.z-mu)*r*g2.z + b2.z;  hr[11] = (v2.w-mu)*r*g2.w + b2.w;
        hr[12] = (v3.x-mu)*r*g3.x + b3.x;  hr[13] = (v3.y-mu)*r*g3.y + b3.y;
        hr[14] = (v3.z-mu)*r*g3.z + b3.z;  hr[15] = (v3.w-mu)*r*g3.w + b3.w;
    }
    __syncthreads();

    // ---- output projection (into Y1, stride 65) + transposed store ----
    gemm64x2<false, false>(T, 68, out_w, 64, out_b, Y1, 65, tid);
    __syncthreads();
    float* og = out + (size_t)b * 4096;
    for (int idx4 = tid; idx4 < 1024; idx4 += NT) {
        int c = idx4 >> 4, n = (idx4 & 15) << 2;
        float4 v;
        v.x = Y1[(n+0)*65 + c];
        v.y = Y1[(n+1)*65 + c];
        v.z = Y1[(n+2)*65 + c];
        v.w = Y1[(n+3)*65 + c];
        *((float4*)og + idx4) = v;
    }
}

// ---------------- launch ----------------
extern "C" void kernel_launch(void* const* d_in, const int* in_sizes, int n_in,
                              void* d_out, int out_size)
{
    const float* x         = (const float*)d_in[0];
    const float* points    = (const float*)d_in[1];
    const float* conv1_w   = (const float*)d_in[2];
    const float* conv1_b   = (const float*)d_in[3];
    const float* conv2_w   = (const float*)d_in[4];
    const float* conv2_b   = (const float*)d_in[5];
    const float* pattern   = (const float*)d_in[6];
    const float* pm1_w     = (const float*)d_in[7];
    const float* pm1_b     = (const float*)d_in[8];
    const float* pm2_w     = (const float*)d_in[9];
    const float* pm2_b     = (const float*)d_in[10];
    const float* q_w       = (const float*)d_in[11];
    const float* q_b       = (const float*)d_in[12];
    const float* k_w       = (const float*)d_in[13];
    const float* k_b       = (const float*)d_in[14];
    const float* v_w       = (const float*)d_in[15];
    const float* v_b       = (const float*)d_in[16];
    const float* in_w      = (const float*)d_in[17];
    const float* in_b      = (const float*)d_in[18];
    const float* mo_w      = (const float*)d_in[19];
    const float* mo_b      = (const float*)d_in[20];
    const float* out_w     = (const float*)d_in[21];
    const float* out_b     = (const float*)d_in[22];
    const float* ln_g      = (const float*)d_in[23];
    const float* ln_b      = (const float*)d_in[24];
    const int*   adjacency = (const int*)d_in[25];

    int B = in_sizes[0] / 4096;
    size_t smem = SMEM_FLOATS * sizeof(float);
    cudaFuncSetAttribute(esa_main_kernel, cudaFuncAttributeMaxDynamicSharedMemorySize, (int)smem);

    esa_prep_kernel<<<24, NT>>>(points, adjacency, in_w, in_b, pattern, pm1_w, pm1_b,
                                q_w, q_b, k_w, k_b, v_w, v_b);
    esa_main_kernel<<<B, NT, smem>>>(x, conv1_w, conv1_b, conv2_w, conv2_b,
                                     pm1_w, pm2_w, pm2_b, mo_w, mo_b,
                                     out_w, out_b, ln_g, ln_b, (float*)d_out);
}

// round 5
// speedup vs baseline: 2.2919x; 2.2919x over previous
#include <cuda_runtime.h>
#include <math.h>

#define NT 256
typedef unsigned long long u64;

// f32x2 packed math (Blackwell): two fp32 FMAs per instruction
#define FMA2(d,a,b)  asm("fma.rn.f32x2 %0, %1, %2, %0;" : "+l"(d) : "l"(a), "l"(b))
#define UNPK(lo,hi,p) asm("mov.b64 {%0,%1}, %2;" : "=f"(lo), "=f"(hi) : "l"(p))
#define PK(p,lo,hi)   asm("mov.b64 %0, {%1,%2};" : "=l"(p) : "f"(lo), "f"(hi))

// ---------------- device scratch ----------------
__device__ __align__(16) float g_geo[4096];
__device__ __align__(16) float g_p16[4096];   // pattern part of pm1 + pm1_b per (n,j)
__device__ __align__(16) float g_wq[4096];
__device__ __align__(16) float g_wk[4096];
__device__ __align__(16) float g_wv[4096];
__device__ __align__(16) float g_bq[64];
__device__ __align__(16) float g_bk[64];
__device__ __align__(16) float g_bv[64];

// ---------------- prep: geo, P16, fused QKV weights ----------------
__global__ void esa_prep_kernel(const float* __restrict__ points,
                                const int*   __restrict__ adjacency,
                                const float* __restrict__ in_w,
                                const float* __restrict__ in_b,
                                const float* __restrict__ pattern,
                                const float* __restrict__ pm1_w,
                                const float* __restrict__ pm1_b,
                                const float* __restrict__ q_w, const float* __restrict__ q_b,
                                const float* __restrict__ k_w, const float* __restrict__ k_b,
                                const float* __restrict__ v_w, const float* __restrict__ v_b)
{
    const int gtid = blockIdx.x * blockDim.x + threadIdx.x;
    const int gstride = gridDim.x * blockDim.x;
    const float scale = 0.3535533905932738f; // 1/sqrt(8)

    for (int idx = gtid; idx < 4096; idx += gstride) {
        int n = idx >> 6, m = idx & 63;
        float dx = points[n*3+0] - points[m*3+0];
        float dy = points[n*3+1] - points[m*3+1];
        float dz = points[n*3+2] - points[m*3+2];
        float dist = sqrtf(dx*dx + dy*dy + dz*dz + 1e-12f);
        g_geo[idx] = (adjacency[idx] > 0) ? 0.5f : (-0.1f / (1.0f + dist));
    }
    // P16[n][j] = pm1_b[j] + sum_p pattern[n][p] * pm1_w[j][64+p]
    for (int idx = gtid; idx < 4096; idx += gstride) {
        int n = idx >> 6, j = idx & 63;
        float s = pm1_b[j];
        const float* wr = pm1_w + j*80 + 64;
        const float* pr = pattern + n*16;
        #pragma unroll
        for (int p = 0; p < 16; p++) s += pr[p] * wr[p];
        g_p16[idx] = s;
    }
    // W_eff[o][u] = sum_t in_w[o][t] * x_w[t][u]   (q scaled by 1/sqrt(D))
    for (int idx = gtid; idx < 3*4096; idx += gstride) {
        int which = idx >> 12;
        int o = (idx >> 6) & 63;
        int u = idx & 63;
        const float* wi = in_w + which*4096 + o*64;
        const float* wx = (which==0) ? q_w : (which==1) ? k_w : v_w;
        float s = 0.f;
        #pragma unroll 4
        for (int t = 0; t < 64; t++) s += wi[t] * wx[t*64 + u];
        if (which == 0) s *= scale;
        float* dst = (which==0) ? g_wq : (which==1) ? g_wk : g_wv;
        dst[o*64 + u] = s;
    }
    for (int idx = gtid; idx < 192; idx += gstride) {
        int which = idx >> 6, o = idx & 63;
        const float* wi = in_w + which*4096 + o*64;
        const float* bx = (which==0) ? q_b : (which==1) ? k_b : v_b;
        float s = in_b[which*64 + o];
        for (int t = 0; t < 64; t++) s += wi[t] * bx[t];
        if (which == 0) s *= scale;
        float* dst = (which==0) ? g_bq : (which==1) ? g_bk : g_bv;
        dst[o] = s;
    }
}

// ---------------- weight prefetch (global -> regs -> smem W, stride 68) ----------------
__device__ __forceinline__ void pre_ld(const float* __restrict__ src, int sstr,
                                       float4* r, int tid) {
    #pragma unroll
    for (int i = 0; i < 4; i++) {
        int idx4 = tid + i*NT;
        int rr = idx4 >> 4, cc = (idx4 & 15) << 2;
        r[i] = __ldg((const float4*)(src + rr*sstr + cc));
    }
}
__device__ __forceinline__ void pre_st(float* __restrict__ Wd, const float4* r, int tid) {
    #pragma unroll
    for (int i = 0; i < 4; i++) {
        int idx4 = tid + i*NT;
        int rr = idx4 >> 4, cc = (idx4 & 15) << 2;
        *(float4*)(Wd + rr*68 + cc) = r[i];
    }
}

// ---------------- f32x2 GEMM, weights in smem (stride 68) ----------------
// out[n][j] = act(bias + in[n][:] . W[j][:]), K=64. BIASMAT: bias = g_p16 matrix.
template<bool RELU, bool BIASMAT>
__device__ __forceinline__ void gemm_s(const float* __restrict__ in, int sin,
                                       const float* __restrict__ W,
                                       const float* __restrict__ bias,
                                       float* __restrict__ outp, int so, int tid)
{
    const int n0 = (tid >> 4) << 2;
    const int j0 = tid & 15;
    u64 acc[4][4];
    #pragma unroll
    for (int i = 0; i < 4; i++)
        #pragma unroll
        for (int j = 0; j < 4; j++) acc[i][j] = 0ull;

    const float* ap = in + n0*sin;
    const float* wp = W + j0*68;
    #pragma unroll 4
    for (int k = 0; k < 64; k += 4) {
        ulonglong2 a[4], b[4];
        a[0] = *(const ulonglong2*)(ap + k);
        a[1] = *(const ulonglong2*)(ap + sin + k);
        a[2] = *(const ulonglong2*)(ap + 2*sin + k);
        a[3] = *(const ulonglong2*)(ap + 3*sin + k);
        b[0] = *(const ulonglong2*)(wp + k);
        b[1] = *(const ulonglong2*)(wp + 16*68 + k);
        b[2] = *(const ulonglong2*)(wp + 32*68 + k);
        b[3] = *(const ulonglong2*)(wp + 48*68 + k);
        #pragma unroll
        for (int i = 0; i < 4; i++)
            #pragma unroll
            for (int j = 0; j < 4; j++) {
                FMA2(acc[i][j], a[i].x, b[j].x);
                FMA2(acc[i][j], a[i].y, b[j].y);
            }
    }
    #pragma unroll
    for (int j = 0; j < 4; j++) {
        int jj = j0 + 16*j;
        float bj = BIASMAT ? 0.f : __ldg(bias + jj);
        #pragma unroll
        for (int i = 0; i < 4; i++) {
            float lo, hi; UNPK(lo, hi, acc[i][j]);
            float v = lo + hi + bj;
            if (BIASMAT) v += __ldg(bias + (n0+i)*64 + jj);
            if (RELU) v = fmaxf(v, 0.f);
            outp[(n0+i)*so + jj] = v;
        }
    }
}

// mo projection with fused +geo +residual epilogue (W in smem stride 68)
__device__ __forceinline__ void gemm_mo_s(const float* __restrict__ in,
                                          const float* __restrict__ W,
                                          const float* __restrict__ mo_b,
                                          const float* __restrict__ pf,
                                          float* __restrict__ outp, int tid)
{
    const int n0 = (tid >> 4) << 2;
    const int j0 = tid & 15;
    u64 acc[4][4];
    #pragma unroll
    for (int i = 0; i < 4; i++)
        #pragma unroll
        for (int j = 0; j < 4; j++) acc[i][j] = 0ull;

    const float* ap = in + n0*68;
    const float* wp = W + j0*68;
    #pragma unroll 4
    for (int k = 0; k < 64; k += 4) {
        ulonglong2 a[4], b[4];
        a[0] = *(const ulonglong2*)(ap + k);
        a[1] = *(const ulonglong2*)(ap + 68 + k);
        a[2] = *(const ulonglong2*)(ap + 136 + k);
        a[3] = *(const ulonglong2*)(ap + 204 + k);
        b[0] = *(const ulonglong2*)(wp + k);
        b[1] = *(const ulonglong2*)(wp + 16*68 + k);
        b[2] = *(const ulonglong2*)(wp + 32*68 + k);
        b[3] = *(const ulonglong2*)(wp + 48*68 + k);
        #pragma unroll
        for (int i = 0; i < 4; i++)
            #pragma unroll
            for (int j = 0; j < 4; j++) {
                FMA2(acc[i][j], a[i].x, b[j].x);
                FMA2(acc[i][j], a[i].y, b[j].y);
            }
    }
    #pragma unroll
    for (int j = 0; j < 4; j++) {
        int jj = j0 + 16*j;
        float bj = __ldg(mo_b + jj);
        #pragma unroll
        for (int i = 0; i < 4; i++) {
            int nn = n0 + i;
            float lo, hi; UNPK(lo, hi, acc[i][j]);
            outp[nn*68 + jj] = lo + hi + bj + __ldg(g_geo + nn*64 + jj) + pf[nn*68 + jj];
        }
    }
}

// conv tap macro: 4 outputs per thread with shifted 3-tap window
#define CONVTAP(XP, CC, W0m, W1m, W2m) { \
    const float* xr = (XP) + (CC)*68 + base; \
    float4 xv = *(const float4*)xr; float2 xt = *(const float2*)(xr+4); \
    a0 += (W0m)*xv.x + (W1m)*xv.y + (W2m)*xv.z; \
    a1 += (W0m)*xv.y + (W1m)*xv.z + (W2m)*xv.w; \
    a2 += (W0m)*xv.z + (W1m)*xv.w + (W2m)*xt.x; \
    a3 += (W0m)*xv.w + (W1m)*xt.x + (W2m)*xt.y; }

// gemm phase with weight prefetch for the NEXT gemm (double-buffered)
#define GPHASE(RELU, BM, IN, SIN, WCUR, BIAS, OUT, SO, NXT, NSTR, WNXT) { \
    float4 pf4[4]; pre_ld(NXT, NSTR, pf4, tid); \
    gemm_s<RELU, BM>(IN, SIN, WCUR, BIAS, OUT, SO, tid); \
    pre_st(WNXT, pf4, tid); \
    __syncthreads(); }

// ---------------- main fused kernel: one CTA per batch element ----------------
// smem (floats): X 0(4352) | Y1 4352(1088) | CB 5440(4352) | T 9792(4352)
//                | PF 14144(4352) | W0 18496(4352) | W1 22848(4352)
#define SMEM_FLOATS 27200

__global__ void __launch_bounds__(NT, 2)
esa_main_kernel(const float* __restrict__ x,
                const float* __restrict__ conv1_w, const float* __restrict__ conv1_b,
                const float* __restrict__ conv2_w, const float* __restrict__ conv2_b,
                const float* __restrict__ pm1_w,
                const float* __restrict__ pm2_w, const float* __restrict__ pm2_b,
                const float* __restrict__ mo_w,  const float* __restrict__ mo_b,
                const float* __restrict__ out_w, const float* __restrict__ out_b,
                const float* __restrict__ ln_g,  const float* __restrict__ ln_b,
                float* __restrict__ out)
{
    extern __shared__ float sm[];
    const int tid = threadIdx.x;
    const int b = blockIdx.x;
    float* X  = sm;
    float* Y1 = sm + 4352;
    float* CB = sm + 5440;
    float* T  = sm + 9792;
    float* PF = sm + 14144;
    float* W0 = sm + 18496;
    float* W1 = sm + 22848;

    // ---- load x + stage pm1 (cols 0..63 of 80-wide rows) into W0 up front ----
    {
        float4 pw[4]; pre_ld(pm1_w, 80, pw, tid);
        const float* xg = x + (size_t)b * 4096;
        for (int idx4 = tid; idx4 < 1024; idx4 += NT) {
            float4 v = __ldg((const float4*)xg + idx4);
            int c = idx4 >> 4, n = (idx4 & 15) << 2;
            float* r = X + c*68 + 1 + n;
            r[0] = v.x; r[1] = v.y; r[2] = v.z; r[3] = v.w;
        }
        pre_st(W0, pw, tid);
        if (tid < 64) { X[tid*68] = 0.f; X[tid*68 + 65] = 0.f; }
        if (tid < 16) { Y1[tid*68] = 0.f; Y1[tid*68 + 65] = 0.f; }
    }
    __syncthreads();

    // ---- 4-scale conv stack (weights from global, warp-uniform __ldg) ----
    for (int s = 0; s < 4; s++) {
        {
            int o = tid >> 4, nq = tid & 15, base = nq*4;
            const float* wr = conv1_w + s*3072 + o*192;
            float a0=0.f, a1=0.f, a2=0.f, a3=0.f;
            #pragma unroll 4
            for (int c = 0; c < 64; c += 4) {
                float4 wA = __ldg((const float4*)(wr + c*3));
                float4 wB = __ldg((const float4*)(wr + c*3 + 4));
                float4 wC = __ldg((const float4*)(wr + c*3 + 8));
                CONVTAP(X, c+0, wA.x, wA.y, wA.z);
                CONVTAP(X, c+1, wA.w, wB.x, wB.y);
                CONVTAP(X, c+2, wB.z, wB.w, wC.x);
                CONVTAP(X, c+3, wC.y, wC.z, wC.w);
            }
            float bb = __ldg(conv1_b + s*16 + o);
            float* yr = Y1 + o*68 + 1 + base;
            yr[0] = fmaxf(a0+bb, 0.f); yr[1] = fmaxf(a1+bb, 0.f);
            yr[2] = fmaxf(a2+bb, 0.f); yr[3] = fmaxf(a3+bb, 0.f);
        }
        __syncthreads();
        {
            int o = tid >> 4, nq = tid & 15, base = nq*4;
            const float* wr = conv2_w + s*768 + o*48;
            float a0=0.f, a1=0.f, a2=0.f, a3=0.f;
            #pragma unroll
            for (int c = 0; c < 16; c += 4) {
                float4 wA = __ldg((const float4*)(wr + c*3));
                float4 wB = __ldg((const float4*)(wr + c*3 + 4));
                float4 wC = __ldg((const float4*)(wr + c*3 + 8));
                CONVTAP(Y1, c+0, wA.x, wA.y, wA.z);
                CONVTAP(Y1, c+1, wA.w, wB.x, wB.y);
                CONVTAP(Y1, c+2, wB.z, wB.w, wC.x);
                CONVTAP(Y1, c+3, wC.y, wC.z, wC.w);
            }
            float bb = __ldg(conv2_b + s*16 + o);
            int ch = s*16 + o;
            CB[(base+0)*68 + ch] = fmaxf(a0+bb, 0.f);
            CB[(base+1)*68 + ch] = fmaxf(a1+bb, 0.f);
            CB[(base+2)*68 + ch] = fmaxf(a2+bb, 0.f);
            CB[(base+3)*68 + ch] = fmaxf(a3+bb, 0.f);
        }
        __syncthreads();
    }

    // ---- GEMM chain, double-buffered weights ----
    // p1: pm1 (W0): CB -> T (relu, P16 bias matrix); prefetch pm2 -> W1
    GPHASE(true,  true,  CB, 68, W0, g_p16,  T,  68, pm2_w, 64, W1);
    // p2: pm2 (W1): T -> PF; prefetch wq -> W0
    GPHASE(false, false, T,  68, W1, pm2_b,  PF, 68, g_wq,  64, W0);
    // p3: Q (W0): PF -> CB; prefetch wk -> W1
    GPHASE(false, false, PF, 68, W0, g_bq,   CB, 68, g_wk,  64, W1);
    // p4: K (W1): PF -> T; prefetch wv -> W0
    GPHASE(false, false, PF, 68, W1, g_bk,   T,  68, g_wv,  64, W0);
    // p5: V (W0): PF -> X; prefetch mo -> W1
    GPHASE(false, false, PF, 68, W0, g_bv,   X,  68, mo_w,  64, W1);

    // ---- attention: thread = (n, head); warp shares head -> broadcast K/V ----
    // CTX overwrites Q in place (single owner per cell).
    {
        const int n  = tid & 63;
        const int hb = tid >> 6;       // 0..3
        #pragma unroll
        for (int it = 0; it < 2; it++) {
            const int h8 = (hb + 4*it) * 8;
            float* qr = CB + n*68 + h8;
            ulonglong2 qa = *(const ulonglong2*)qr;
            ulonglong2 qb = *(const ulonglong2*)(qr + 4);
            float sc[64];
            float mx = -3.0e38f;
            #pragma unroll
            for (int m = 0; m < 64; m++) {
                const float* kr = T + m*68 + h8;
                ulonglong2 ka = *(const ulonglong2*)kr;
                ulonglong2 kb = *(const ulonglong2*)(kr + 4);
                u64 d = 0ull;
                FMA2(d, qa.x, ka.x); FMA2(d, qa.y, ka.y);
                FMA2(d, qb.x, kb.x); FMA2(d, qb.y, kb.y);
                float lo, hi; UNPK(lo, hi, d);
                float sv = lo + hi;
                sc[m] = sv; mx = fmaxf(mx, sv);
            }
            u64 c01 = 0ull, c23 = 0ull, c45 = 0ull, c67 = 0ull;
            float sum = 0.f;
            #pragma unroll
            for (int m = 0; m < 64; m++) {
                float e = __expf(sc[m] - mx);
                sum += e;
                u64 ee; PK(ee, e, e);
                const float* vr = X + m*68 + h8;
                ulonglong2 va = *(const ulonglong2*)vr;
                ulonglong2 vb = *(const ulonglong2*)(vr + 4);
                FMA2(c01, ee, va.x); FMA2(c23, ee, va.y);
                FMA2(c45, ee, vb.x); FMA2(c67, ee, vb.y);
            }
            float inv = 1.f / sum;
            float c0,c1,c2,c3,c4,c5,c6,c7;
            UNPK(c0,c1,c01); UNPK(c2,c3,c23); UNPK(c4,c5,c45); UNPK(c6,c7,c67);
            float4 o1 = make_float4(c0*inv, c1*inv, c2*inv, c3*inv);
            float4 o2 = make_float4(c4*inv, c5*inv, c6*inv, c7*inv);
            *(float4*)qr       = o1;
            *(float4*)(qr + 4) = o2;
        }
    }
    __syncthreads();

    // ---- p6: mo (W1): CB -> T with +geo +residual; prefetch out_w -> W0 ----
    {
        float4 pf4[4]; pre_ld(out_w, 64, pf4, tid);
        gemm_mo_s(CB, W1, mo_b, PF, T, tid);
        pre_st(W0, pf4, tid);
        __syncthreads();
    }

    // ---- LayerNorm over C (in place in T) ----
    {
        int n = tid >> 2, g = tid & 3;
        float* hr = T + n*68 + g*16;
        float4 v0 = *(const float4*)(hr);
        float4 v1 = *(const float4*)(hr + 4);
        float4 v2 = *(const float4*)(hr + 8);
        float4 v3 = *(const float4*)(hr + 12);
        float s  = v0.x+v0.y+v0.z+v0.w + v1.x+v1.y+v1.z+v1.w
                 + v2.x+v2.y+v2.z+v2.w + v3.x+v3.y+v3.z+v3.w;
        float s2 = v0.x*v0.x+v0.y*v0.y+v0.z*v0.z+v0.w*v0.w
                 + v1.x*v1.x+v1.y*v1.y+v1.z*v1.z+v1.w*v1.w
                 + v2.x*v2.x+v2.y*v2.y+v2.z*v2.z+v2.w*v2.w
                 + v3.x*v3.x+v3.y*v3.y+v3.z*v3.z+v3.w*v3.w;
        s  += __shfl_xor_sync(0xffffffffu, s, 1);
        s  += __shfl_xor_sync(0xffffffffu, s, 2);
        s2 += __shfl_xor_sync(0xffffffffu, s2, 1);
        s2 += __shfl_xor_sync(0xffffffffu, s2, 2);
        float mu  = s * 0.015625f;
        float var = s2 * 0.015625f - mu*mu;
        float r = rsqrtf(var + 1e-5f);
        int cb = g*16;
        float4 g0 = __ldg((const float4*)(ln_g + cb));
        float4 g1 = __ldg((const float4*)(ln_g + cb + 4));
        float4 g2 = __ldg((const float4*)(ln_g + cb + 8));
        float4 g3 = __ldg((const float4*)(ln_g + cb + 12));
        float4 b0 = __ldg((const float4*)(ln_b + cb));
        float4 b1 = __ldg((const float4*)(ln_b + cb + 4));
        float4 b2 = __ldg((const float4*)(ln_b + cb + 8));
        float4 b3 = __ldg((const float4*)(ln_b + cb + 12));
        hr[0]  = (v0.x-mu)*r*g0.x + b0.x;  hr[1]  = (v0.y-mu)*r*g0.y + b0.y;
        hr[2]  = (v0.z-mu)*r*g0.z + b0.z;  hr[3]  = (v0.w-mu)*r*g0.w + b0.w;
        hr[4]  = (v1.x-mu)*r*g1.x + b1.x;  hr[5]  = (v1.y-mu)*r*g1.y + b1.y;
        hr[6]  = (v1.z-mu)*r*g1.z + b1.z;  hr[7]  = (v1.w-mu)*r*g1.w + b1.w;
        hr[8]  = (v2.x-mu)*r*g2.x + b2.x;  hr[9]  = (v2.y-mu)*r*g2.y + b2.y;
        hr[10] = (v2.z-mu)*r*g2.z + b2.z;  hr[11] = (v2.w-mu)*r*g2.w + b2.w;
        hr[12] = (v3.x-mu)*r*g3.x + b3.x;  hr[13] = (v3.y-mu)*r*g3.y + b3.y;
        hr[14] = (v3.z-mu)*r*g3.z + b3.z;  hr[15] = (v3.w-mu)*r*g3.w + b3.w;
    }
    __syncthreads();

    // ---- p7: out (W0): T -> X (stride 65, V dead) ----
    gemm_s<false, false>(T, 68, W0, out_b, X, 65, tid);
    __syncthreads();

    // ---- transposed store ----
    float* og = out + (size_t)b * 4096;
    for (int idx4 = tid; idx4 < 1024; idx4 += NT) {
        int c = idx4 >> 4, n = (idx4 & 15) << 2;
        float4 v;
        v.x = X[(n+0)*65 + c];
        v.y = X[(n+1)*65 + c];
        v.z = X[(n+2)*65 + c];
        v.w = X[(n+3)*65 + c];
        *((float4*)og + idx4) = v;
    }
}

// ---------------- launch ----------------
extern "C" void kernel_launch(void* const* d_in, const int* in_sizes, int n_in,
                              void* d_out, int out_size)
{
    const float* x         = (const float*)d_in[0];
    const float* points    = (const float*)d_in[1];
    const float* conv1_w   = (const float*)d_in[2];
    const float* conv1_b   = (const float*)d_in[3];
    const float* conv2_w   = (const float*)d_in[4];
    const float* conv2_b   = (const float*)d_in[5];
    const float* pattern   = (const float*)d_in[6];
    const float* pm1_w     = (const float*)d_in[7];
    const float* pm1_b     = (const float*)d_in[8];
    const float* pm2_w     = (const float*)d_in[9];
    const float* pm2_b     = (const float*)d_in[10];
    const float* q_w       = (const float*)d_in[11];
    const float* q_b       = (const float*)d_in[12];
    const float* k_w       = (const float*)d_in[13];
    const float* k_b       = (const float*)d_in[14];
    const float* v_w       = (const float*)d_in[15];
    const float* v_b       = (const float*)d_in[16];
    const float* in_w      = (const float*)d_in[17];
    const float* in_b      = (const float*)d_in[18];
    const float* mo_w      = (const float*)d_in[19];
    const float* mo_b      = (const float*)d_in[20];
    const float* out_w     = (const float*)d_in[21];
    const float* out_b     = (const float*)d_in[22];
    const float* ln_g      = (const float*)d_in[23];
    const float* ln_b      = (const float*)d_in[24];
    const int*   adjacency = (const int*)d_in[25];

    int B = in_sizes[0] / 4096;
    size_t smem = SMEM_FLOATS * sizeof(float);
    cudaFuncSetAttribute(esa_main_kernel, cudaFuncAttributeMaxDynamicSharedMemorySize, (int)smem);

    esa_prep_kernel<<<24, NT>>>(points, adjacency, in_w, in_b, pattern, pm1_w, pm1_b,
                                q_w, q_b, k_w, k_b, v_w, v_b);
    esa_main_kernel<<<B, NT, smem>>>(x, conv1_w, conv1_b, conv2_w, conv2_b,
                                     pm1_w, pm2_w, pm2_b, mo_w, mo_b,
                                     out_w, out_b, ln_g, ln_b, (float*)d_out);
}

// round 6
// speedup vs baseline: 2.3128x; 1.0091x over previous
#include <cuda_runtime.h>
#include <math.h>

#define NT 256
typedef unsigned long long u64;

// f32x2 packed math (Blackwell): two fp32 FMAs per instruction
#define FMA2(d,a,b)  asm("fma.rn.f32x2 %0, %1, %2, %0;" : "+l"(d) : "l"(a), "l"(b))
#define UNPK(lo,hi,p) asm("mov.b64 {%0,%1}, %2;" : "=f"(lo), "=f"(hi) : "l"(p))
#define PK(p,lo,hi)   asm("mov.b64 %0, {%1,%2};" : "=l"(p) : "f"(lo), "f"(hi))

// ---------------- device scratch ----------------
__device__ __align__(16) float g_geo[4096];
__device__ __align__(16) float g_p16[4096];   // pattern part of pm1 + pm1_b per (n,j)
__device__ __align__(16) float g_wq[4096];
__device__ __align__(16) float g_wk[4096];
__device__ __align__(16) float g_wv[4096];
__device__ __align__(16) float g_bq[64];
__device__ __align__(16) float g_bk[64];
__device__ __align__(16) float g_bv[64];

// ---------------- prep: geo, P16, fused QKV weights ----------------
__global__ void esa_prep_kernel(const float* __restrict__ points,
                                const int*   __restrict__ adjacency,
                                const float* __restrict__ in_w,
                                const float* __restrict__ in_b,
                                const float* __restrict__ pattern,
                                const float* __restrict__ pm1_w,
                                const float* __restrict__ pm1_b,
                                const float* __restrict__ q_w, const float* __restrict__ q_b,
                                const float* __restrict__ k_w, const float* __restrict__ k_b,
                                const float* __restrict__ v_w, const float* __restrict__ v_b)
{
    const int gtid = blockIdx.x * blockDim.x + threadIdx.x;
    const int gstride = gridDim.x * blockDim.x;
    const float scale = 0.3535533905932738f; // 1/sqrt(8)

    for (int idx = gtid; idx < 4096; idx += gstride) {
        int n = idx >> 6, m = idx & 63;
        float dx = points[n*3+0] - points[m*3+0];
        float dy = points[n*3+1] - points[m*3+1];
        float dz = points[n*3+2] - points[m*3+2];
        float dist = sqrtf(dx*dx + dy*dy + dz*dz + 1e-12f);
        g_geo[idx] = (adjacency[idx] > 0) ? 0.5f : (-0.1f / (1.0f + dist));
    }
    // P16[n][j] = pm1_b[j] + sum_p pattern[n][p] * pm1_w[j][64+p]
    for (int idx = gtid; idx < 4096; idx += gstride) {
        int n = idx >> 6, j = idx & 63;
        float s = pm1_b[j];
        const float* wr = pm1_w + j*80 + 64;
        const float* pr = pattern + n*16;
        #pragma unroll
        for (int p = 0; p < 16; p++) s += pr[p] * wr[p];
        g_p16[idx] = s;
    }
    // W_eff[o][u] = sum_t in_w[o][t] * x_w[t][u]   (q scaled by 1/sqrt(D))
    for (int idx = gtid; idx < 3*4096; idx += gstride) {
        int which = idx >> 12;
        int o = (idx >> 6) & 63;
        int u = idx & 63;
        const float* wi = in_w + which*4096 + o*64;
        const float* wx = (which==0) ? q_w : (which==1) ? k_w : v_w;
        float s = 0.f;
        #pragma unroll 4
        for (int t = 0; t < 64; t++) s += wi[t] * wx[t*64 + u];
        if (which == 0) s *= scale;
        float* dst = (which==0) ? g_wq : (which==1) ? g_wk : g_wv;
        dst[o*64 + u] = s;
    }
    for (int idx = gtid; idx < 192; idx += gstride) {
        int which = idx >> 6, o = idx & 63;
        const float* wi = in_w + which*4096 + o*64;
        const float* bx = (which==0) ? q_b : (which==1) ? k_b : v_b;
        float s = in_b[which*64 + o];
        for (int t = 0; t < 64; t++) s += wi[t] * bx[t];
        if (which == 0) s *= scale;
        float* dst = (which==0) ? g_bq : (which==1) ? g_bk : g_bv;
        dst[o] = s;
    }
}

// ---------------- weight staging ----------------
// full-CTA version (x-load phase): 4 float4 per thread
__device__ __forceinline__ void pre_ld(const float* __restrict__ src, int sstr,
                                       float4* r, int tid) {
    #pragma unroll
    for (int i = 0; i < 4; i++) {
        int idx4 = tid + i*NT;
        int rr = idx4 >> 4, cc = (idx4 & 15) << 2;
        r[i] = __ldg((const float4*)(src + rr*sstr + cc));
    }
}
__device__ __forceinline__ void pre_st(float* __restrict__ Wd, const float4* r, int tid) {
    #pragma unroll
    for (int i = 0; i < 4; i++) {
        int idx4 = tid + i*NT;
        int rr = idx4 >> 4, cc = (idx4 & 15) << 2;
        *(float4*)(Wd + rr*68 + cc) = r[i];
    }
}
// half-CTA version (prefetch warps, stride-64 sources): 8 float4 per thread
__device__ __forceinline__ void stage_w_half(const float* __restrict__ src,
                                             float* __restrict__ Wd, int t2) {
    float4 r[8];
    #pragma unroll
    for (int i = 0; i < 8; i++) {
        int idx4 = t2 + i*128;
        int rr = idx4 >> 4, cc = (idx4 & 15) << 2;
        r[i] = __ldg((const float4*)(src + rr*64 + cc));
    }
    #pragma unroll
    for (int i = 0; i < 8; i++) {
        int idx4 = t2 + i*128;
        int rr = idx4 >> 4, cc = (idx4 & 15) << 2;
        *(float4*)(Wd + rr*68 + cc) = r[i];
    }
}

// ---------------- f32x2 GEMM, 4x8 tiles on 128 threads ----------------
// rows r+16i (r=tid>>3), cols j0+8j (j0=tid&7). Weights in smem stride 68.
// b-loads: 8 distinct rows x 16B = 128B = 1 wavefront. a-loads: 4 rows, banks 4r+k.
template<bool RELU, bool BIASMAT>
__device__ __forceinline__ void gemm48(const float* __restrict__ in, int sin,
                                       const float* __restrict__ W,
                                       const float* __restrict__ bias,
                                       float* __restrict__ outp, int so, int tid)
{
    const int r  = tid >> 3;
    const int j0 = tid & 7;
    u64 acc[4][8];
    #pragma unroll
    for (int i = 0; i < 4; i++)
        #pragma unroll
        for (int j = 0; j < 8; j++) acc[i][j] = 0ull;

    const float* ap = in + r*sin;
    const float* wp = W + j0*68;
    #pragma unroll 4
    for (int k = 0; k < 64; k += 4) {
        ulonglong2 a[4];
        a[0] = *(const ulonglong2*)(ap + k);
        a[1] = *(const ulonglong2*)(ap + 16*sin + k);
        a[2] = *(const ulonglong2*)(ap + 32*sin + k);
        a[3] = *(const ulonglong2*)(ap + 48*sin + k);
        #pragma unroll
        for (int j = 0; j < 8; j++) {
            ulonglong2 b = *(const ulonglong2*)(wp + j*8*68 + k);
            #pragma unroll
            for (int i = 0; i < 4; i++) {
                FMA2(acc[i][j], a[i].x, b.x);
                FMA2(acc[i][j], a[i].y, b.y);
            }
        }
    }
    #pragma unroll
    for (int j = 0; j < 8; j++) {
        int jj = j0 + 8*j;
        float bj = BIASMAT ? 0.f : __ldg(bias + jj);
        #pragma unroll
        for (int i = 0; i < 4; i++) {
            int row = r + 16*i;
            float lo, hi; UNPK(lo, hi, acc[i][j]);
            float v = lo + hi + bj;
            if (BIASMAT) v += __ldg(bias + row*64 + jj);
            if (RELU) v = fmaxf(v, 0.f);
            outp[row*so + jj] = v;
        }
    }
}

// mo projection with fused +geo +residual epilogue
__device__ __forceinline__ void gemm_mo48(const float* __restrict__ in,
                                          const float* __restrict__ W,
                                          const float* __restrict__ mo_b,
                                          const float* __restrict__ pf,
                                          float* __restrict__ outp, int tid)
{
    const int r  = tid >> 3;
    const int j0 = tid & 7;
    u64 acc[4][8];
    #pragma unroll
    for (int i = 0; i < 4; i++)
        #pragma unroll
        for (int j = 0; j < 8; j++) acc[i][j] = 0ull;

    const float* ap = in + r*68;
    const float* wp = W + j0*68;
    #pragma unroll 4
    for (int k = 0; k < 64; k += 4) {
        ulonglong2 a[4];
        a[0] = *(const ulonglong2*)(ap + k);
        a[1] = *(const ulonglong2*)(ap + 16*68 + k);
        a[2] = *(const ulonglong2*)(ap + 32*68 + k);
        a[3] = *(const ulonglong2*)(ap + 48*68 + k);
        #pragma unroll
        for (int j = 0; j < 8; j++) {
            ulonglong2 b = *(const ulonglong2*)(wp + j*8*68 + k);
            #pragma unroll
            for (int i = 0; i < 4; i++) {
                FMA2(acc[i][j], a[i].x, b.x);
                FMA2(acc[i][j], a[i].y, b.y);
            }
        }
    }
    #pragma unroll
    for (int j = 0; j < 8; j++) {
        int jj = j0 + 8*j;
        float bj = __ldg(mo_b + jj);
        #pragma unroll
        for (int i = 0; i < 4; i++) {
            int row = r + 16*i;
            float lo, hi; UNPK(lo, hi, acc[i][j]);
            outp[row*68 + jj] = lo + hi + bj + __ldg(g_geo + row*64 + jj) + pf[row*68 + jj];
        }
    }
}

// final projection: write transposed result straight to global (out[c][n])
__device__ __forceinline__ void gemm_out48(const float* __restrict__ in,
                                           const float* __restrict__ W,
                                           const float* __restrict__ bias,
                                           float* __restrict__ og, int tid)
{
    const int r  = tid >> 3;
    const int j0 = tid & 7;
    u64 acc[4][8];
    #pragma unroll
    for (int i = 0; i < 4; i++)
        #pragma unroll
        for (int j = 0; j < 8; j++) acc[i][j] = 0ull;

    const float* ap = in + r*68;
    const float* wp = W + j0*68;
    #pragma unroll 4
    for (int k = 0; k < 64; k += 4) {
        ulonglong2 a[4];
        a[0] = *(const ulonglong2*)(ap + k);
        a[1] = *(const ulonglong2*)(ap + 16*68 + k);
        a[2] = *(const ulonglong2*)(ap + 32*68 + k);
        a[3] = *(const ulonglong2*)(ap + 48*68 + k);
        #pragma unroll
        for (int j = 0; j < 8; j++) {
            ulonglong2 b = *(const ulonglong2*)(wp + j*8*68 + k);
            #pragma unroll
            for (int i = 0; i < 4; i++) {
                FMA2(acc[i][j], a[i].x, b.x);
                FMA2(acc[i][j], a[i].y, b.y);
            }
        }
    }
    #pragma unroll
    for (int j = 0; j < 8; j++) {
        int jj = j0 + 8*j;
        float bj = __ldg(bias + jj);
        #pragma unroll
        for (int i = 0; i < 4; i++) {
            int row = r + 16*i;
            float lo, hi; UNPK(lo, hi, acc[i][j]);
            og[jj*64 + row] = lo + hi + bj;   // out[c=jj][n=row]
        }
    }
}

// conv tap macro: 4 outputs per thread with shifted 3-tap window
#define CONVTAP(XP, CC, W0m, W1m, W2m) { \
    const float* xr = (XP) + (CC)*68 + base; \
    float4 xv = *(const float4*)xr; float2 xt = *(const float2*)(xr+4); \
    a0 += (W0m)*xv.x + (W1m)*xv.y + (W2m)*xv.z; \
    a1 += (W0m)*xv.y + (W1m)*xv.z + (W2m)*xv.w; \
    a2 += (W0m)*xv.z + (W1m)*xv.w + (W2m)*xt.x; \
    a3 += (W0m)*xv.w + (W1m)*xt.x + (W2m)*xt.y; }

// gemm phase: compute warps run GEMM, prefetch warps stage next weights
#define GPHASE(RELU, BM, IN, SIN, WCUR, BIAS, OUT, SO, NXT, WNXT) { \
    if (tid < 128) gemm48<RELU, BM>(IN, SIN, WCUR, BIAS, OUT, SO, tid); \
    else stage_w_half(NXT, WNXT, tid - 128); \
    __syncthreads(); }

// ---------------- main fused kernel: one CTA per batch element ----------------
// smem (floats): X 0(4352) | Y1 4352(1088) | CB 5440(4352) | T 9792(4352)
//                | PF 14144(4352) | W0 18496(4352) | W1 22848(4352)
#define SMEM_FLOATS 27200

__global__ void __launch_bounds__(NT, 2)
esa_main_kernel(const float* __restrict__ x,
                const float* __restrict__ conv1_w, const float* __restrict__ conv1_b,
                const float* __restrict__ conv2_w, const float* __restrict__ conv2_b,
                const float* __restrict__ pm1_w,
                const float* __restrict__ pm2_w, const float* __restrict__ pm2_b,
                const float* __restrict__ mo_w,  const float* __restrict__ mo_b,
                const float* __restrict__ out_w, const float* __restrict__ out_b,
                const float* __restrict__ ln_g,  const float* __restrict__ ln_b,
                float* __restrict__ out)
{
    extern __shared__ float sm[];
    const int tid = threadIdx.x;
    const int b = blockIdx.x;
    float* X  = sm;
    float* Y1 = sm + 4352;
    float* CB = sm + 5440;
    float* T  = sm + 9792;
    float* PF = sm + 14144;
    float* W0 = sm + 18496;
    float* W1 = sm + 22848;

    // ---- load x + stage pm1 (cols 0..63 of 80-wide rows) into W0 ----
    {
        float4 pw[4]; pre_ld(pm1_w, 80, pw, tid);
        const float* xg = x + (size_t)b * 4096;
        for (int idx4 = tid; idx4 < 1024; idx4 += NT) {
            float4 v = __ldg((const float4*)xg + idx4);
            int c = idx4 >> 4, n = (idx4 & 15) << 2;
            float* rr = X + c*68 + 1 + n;
            rr[0] = v.x; rr[1] = v.y; rr[2] = v.z; rr[3] = v.w;
        }
        pre_st(W0, pw, tid);
        if (tid < 64) { X[tid*68] = 0.f; X[tid*68 + 65] = 0.f; }
        if (tid < 16) { Y1[tid*68] = 0.f; Y1[tid*68 + 65] = 0.f; }
    }
    __syncthreads();

    // ---- 4-scale conv stack (weights from global, warp-uniform __ldg) ----
    for (int s = 0; s < 4; s++) {
        {
            int o = tid >> 4, nq = tid & 15, base = nq*4;
            const float* wr = conv1_w + s*3072 + o*192;
            float a0=0.f, a1=0.f, a2=0.f, a3=0.f;
            #pragma unroll 4
            for (int c = 0; c < 64; c += 4) {
                float4 wA = __ldg((const float4*)(wr + c*3));
                float4 wB = __ldg((const float4*)(wr + c*3 + 4));
                float4 wC = __ldg((const float4*)(wr + c*3 + 8));
                CONVTAP(X, c+0, wA.x, wA.y, wA.z);
                CONVTAP(X, c+1, wA.w, wB.x, wB.y);
                CONVTAP(X, c+2, wB.z, wB.w, wC.x);
                CONVTAP(X, c+3, wC.y, wC.z, wC.w);
            }
            float bb = __ldg(conv1_b + s*16 + o);
            float* yr = Y1 + o*68 + 1 + base;
            yr[0] = fmaxf(a0+bb, 0.f); yr[1] = fmaxf(a1+bb, 0.f);
            yr[2] = fmaxf(a2+bb, 0.f); yr[3] = fmaxf(a3+bb, 0.f);
        }
        __syncthreads();
        {
            int o = tid >> 4, nq = tid & 15, base = nq*4;
            const float* wr = conv2_w + s*768 + o*48;
            float a0=0.f, a1=0.f, a2=0.f, a3=0.f;
            #pragma unroll
            for (int c = 0; c < 16; c += 4) {
                float4 wA = __ldg((const float4*)(wr + c*3));
                float4 wB = __ldg((const float4*)(wr + c*3 + 4));
                float4 wC = __ldg((const float4*)(wr + c*3 + 8));
                CONVTAP(Y1, c+0, wA.x, wA.y, wA.z);
                CONVTAP(Y1, c+1, wA.w, wB.x, wB.y);
                CONVTAP(Y1, c+2, wB.z, wB.w, wC.x);
                CONVTAP(Y1, c+3, wC.y, wC.z, wC.w);
            }
            float bb = __ldg(conv2_b + s*16 + o);
            int ch = s*16 + o;
            CB[(base+0)*68 + ch] = fmaxf(a0+bb, 0.f);
            CB[(base+1)*68 + ch] = fmaxf(a1+bb, 0.f);
            CB[(base+2)*68 + ch] = fmaxf(a2+bb, 0.f);
            CB[(base+3)*68 + ch] = fmaxf(a3+bb, 0.f);
        }
        __syncthreads();
    }

    // ---- GEMM chain: compute warps (0-3) + prefetch warps (4-7) ----
    GPHASE(true,  true,  CB, 68, W0, g_p16,  T,  68, pm2_w, W1);  // pm1
    GPHASE(false, false, T,  68, W1, pm2_b,  PF, 68, g_wq,  W0);  // pm2
    GPHASE(false, false, PF, 68, W0, g_bq,   CB, 68, g_wk,  W1);  // Q
    GPHASE(false, false, PF, 68, W1, g_bk,   T,  68, g_wv,  W0);  // K
    GPHASE(false, false, PF, 68, W0, g_bv,   X,  68, mo_w,  W1);  // V

    // ---- attention: thread = (n, head); warp-uniform K/V loads (1 wf each) ----
    // CTX overwrites Q in place (single owner per cell).
    {
        const int n  = tid & 63;
        const int hb = tid >> 6;       // 0..3
        #pragma unroll
        for (int it = 0; it < 2; it++) {
            const int h8 = (hb + 4*it) * 8;
            float* qr = CB + n*68 + h8;
            ulonglong2 qa = *(const ulonglong2*)qr;
            ulonglong2 qb = *(const ulonglong2*)(qr + 4);
            float sc[64];
            float mx = -3.0e38f;
            #pragma unroll
            for (int m = 0; m < 64; m++) {
                const float* kr = T + m*68 + h8;
                ulonglong2 ka = *(const ulonglong2*)kr;
                ulonglong2 kb = *(const ulonglong2*)(kr + 4);
                u64 d = 0ull;
                FMA2(d, qa.x, ka.x); FMA2(d, qa.y, ka.y);
                FMA2(d, qb.x, kb.x); FMA2(d, qb.y, kb.y);
                float lo, hi; UNPK(lo, hi, d);
                float sv = lo + hi;
                sc[m] = sv; mx = fmaxf(mx, sv);
            }
            u64 c01 = 0ull, c23 = 0ull, c45 = 0ull, c67 = 0ull;
            float sum = 0.f;
            #pragma unroll
            for (int m = 0; m < 64; m++) {
                float e = __expf(sc[m] - mx);
                sum += e;
                u64 ee; PK(ee, e, e);
                const float* vr = X + m*68 + h8;
                ulonglong2 va = *(const ulonglong2*)vr;
                ulonglong2 vb = *(const ulonglong2*)(vr + 4);
                FMA2(c01, ee, va.x); FMA2(c23, ee, va.y);
                FMA2(c45, ee, vb.x); FMA2(c67, ee, vb.y);
            }
            float inv = 1.f / sum;
            float c0,c1,c2,c3,c4,c5,c6,c7;
            UNPK(c0,c1,c01); UNPK(c2,c3,c23); UNPK(c4,c5,c45); UNPK(c6,c7,c67);
            float4 o1 = make_float4(c0*inv, c1*inv, c2*inv, c3*inv);
            float4 o2 = make_float4(c4*inv, c5*inv, c6*inv, c7*inv);
            *(float4*)qr       = o1;
            *(float4*)(qr + 4) = o2;
        }
    }
    __syncthreads();

    // ---- mo (W1): CB -> T with +geo +residual; prefetch out_w -> W0 ----
    if (tid < 128) gemm_mo48(CB, W1, mo_b, PF, T, tid);
    else stage_w_half(out_w, W0, tid - 128);
    __syncthreads();

    // ---- LayerNorm over C (in place in T) ----
    {
        int n = tid >> 2, g = tid & 3;
        float* hr = T + n*68 + g*16;
        float4 v0 = *(const float4*)(hr);
        float4 v1 = *(const float4*)(hr + 4);
        float4 v2 = *(const float4*)(hr + 8);
        float4 v3 = *(const float4*)(hr + 12);
        float s  = v0.x+v0.y+v0.z+v0.w + v1.x+v1.y+v1.z+v1.w
                 + v2.x+v2.y+v2.z+v2.w + v3.x+v3.y+v3.z+v3.w;
        float s2 = v0.x*v0.x+v0.y*v0.y+v0.z*v0.z+v0.w*v0.w
                 + v1.x*v1.x+v1.y*v1.y+v1.z*v1.z+v1.w*v1.w
                 + v2.x*v2.x+v2.y*v2.y+v2.z*v2.z+v2.w*v2.w
                 + v3.x*v3.x+v3.y*v3.y+v3.z*v3.z+v3.w*v3.w;
        s  += __shfl_xor_sync(0xffffffffu, s, 1);
        s  += __shfl_xor_sync(0xffffffffu, s, 2);
        s2 += __shfl_xor_sync(0xffffffffu, s2, 1);
        s2 += __shfl_xor_sync(0xffffffffu, s2, 2);
        float mu  = s * 0.015625f;
        float var = s2 * 0.015625f - mu*mu;
        float r = rsqrtf(var + 1e-5f);
        int cb = g*16;
        float4 g0 = __ldg((const float4*)(ln_g + cb));
        float4 g1 = __ldg((const float4*)(ln_g + cb + 4));
        float4 g2 = __ldg((const float4*)(ln_g + cb + 8));
        float4 g3 = __ldg((const float4*)(ln_g + cb + 12));
        float4 b0 = __ldg((const float4*)(ln_b + cb));
        float4 b1 = __ldg((const float4*)(ln_b + cb + 4));
        float4 b2 = __ldg((const float4*)(ln_b + cb + 8));
        float4 b3 = __ldg((const float4*)(ln_b + cb + 12));
        hr[0]  = (v0.x-mu)*r*g0.x + b0.x;  hr[1]  = (v0.y-mu)*r*g0.y + b0.y;
        hr[2]  = (v0.z-mu)*r*g0.z + b0.z;  hr[3]  = (v0.w-mu)*r*g0.w + b0.w;
        hr[4]  = (v1.x-mu)*r*g1.x + b1.x;  hr[5]  = (v1.y-mu)*r*g1.y + b1.y;
        hr[6]  = (v1.z-mu)*r*g1.z + b1.z;  hr[7]  = (v1.w-mu)*r*g1.w + b1.w;
        hr[8]  = (v2.x-mu)*r*g2.x + b2.x;  hr[9]  = (v2.y-mu)*r*g2.y + b2.y;
        hr[10] = (v2.z-mu)*r*g2.z + b2.z;  hr[11] = (v2.w-mu)*r*g2.w + b2.w;
        hr[12] = (v3.x-mu)*r*g3.x + b3.x;  hr[13] = (v3.y-mu)*r*g3.y + b3.y;
        hr[14] = (v3.z-mu)*r*g3.z + b3.z;  hr[15] = (v3.w-mu)*r*g3.w + b3.w;
    }
    __syncthreads();

    // ---- final projection: straight to global, transposed layout ----
    if (tid < 128) gemm_out48(T, W0, out_b, out + (size_t)b * 4096, tid);
}

// ---------------- launch ----------------
extern "C" void kernel_launch(void* const* d_in, const int* in_sizes, int n_in,
                              void* d_out, int out_size)
{
    const float* x         = (const float*)d_in[0];
    const float* points    = (const float*)d_in[1];
    const float* conv1_w   = (const float*)d_in[2];
    const float* conv1_b   = (const float*)d_in[3];
    const float* conv2_w   = (const float*)d_in[4];
    const float* conv2_b   = (const float*)d_in[5];
    const float* pattern   = (const float*)d_in[6];
    const float* pm1_w     = (const float*)d_in[7];
    const float* pm1_b     = (const float*)d_in[8];
    const float* pm2_w     = (const float*)d_in[9];
    const float* pm2_b     = (const float*)d_in[10];
    const float* q_w       = (const float*)d_in[11];
    const float* q_b       = (const float*)d_in[12];
    const float* k_w       = (const float*)d_in[13];
    const float* k_b       = (const float*)d_in[14];
    const float* v_w       = (const float*)d_in[15];
    const float* v_b       = (const float*)d_in[16];
    const float* in_w      = (const float*)d_in[17];
    const float* in_b      = (const float*)d_in[18];
    const float* mo_w      = (const float*)d_in[19];
    const float* mo_b      = (const float*)d_in[20];
    const float* out_w     = (const float*)d_in[21];
    const float* out_b     = (const float*)d_in[22];
    const float* ln_g      = (const float*)d_in[23];
    const float* ln_b      = (const float*)d_in[24];
    const int*   adjacency = (const int*)d_in[25];

    int B = in_sizes[0] / 4096;
    size_t smem = SMEM_FLOATS * sizeof(float);
    cudaFuncSetAttribute(esa_main_kernel, cudaFuncAttributeMaxDynamicSharedMemorySize, (int)smem);

    esa_prep_kernel<<<24, NT>>>(points, adjacency, in_w, in_b, pattern, pm1_w, pm1_b,
                                q_w, q_b, k_w, k_b, v_w, v_b);
    esa_main_kernel<<<B, NT, smem>>>(x, conv1_w, conv1_b, conv2_w, conv2_b,
                                     pm1_w, pm2_w, pm2_b, mo_w, mo_b,
                                     out_w, out_b, ln_g, ln_b, (float*)d_out);
}